// round 11
// baseline (speedup 1.0000x reference)
#include <cuda_runtime.h>

#define N      4096
#define NFEAT  6
#define NB     4096          // fine value-buckets per feature
#define IB     256           // threads per block
#define NBI    16            // i-blocks (256 i each, 1 per thread)
#define NJ     8             // j-chunks
#define JC     512           // j per chunk

// Pairwise partials (sky_sep, mass_sim) per j-chunk
__device__ float2 g_part2[NJ][N];
// Closed-form per-row sums: 0=dt 1=dpsi 2=dra 3=ddec 4=freq_ov 5=dist_ratio
__device__ float  g_closed[NFEAT][N];

__device__ __forceinline__ float f_ex2(float x) {
    float r; asm("ex2.approx.ftz.f32 %0, %1;" : "=f"(r) : "f"(x)); return r;
}
__device__ __forceinline__ float f_lg2(float x) {
    float r; asm("lg2.approx.ftz.f32 %0, %1;" : "=f"(r) : "f"(x)); return r;
}
__device__ __forceinline__ float f_rcp(float x) {
    float r; asm("rcp.approx.ftz.f32 %0, %1;" : "=f"(r) : "f"(x)); return r;
}
__device__ __forceinline__ float f_sqrt(float x) {
    float r; asm("sqrt.approx.ftz.f32 %0, %1;" : "=f"(r) : "f"(x)); return r;
}

// pairwise needs (ra, dec, mc30)
__device__ __forceinline__ float3 pair_inv(const float* __restrict__ p, int idx) {
    const float* q = p + idx * 15;
    float m1 = q[0] * 95.0f + 5.0f;
    float m2 = q[1] * 95.0f + 5.0f;
    float mc = f_ex2(0.6f * f_lg2(m1 * m2) - 0.2f * f_lg2(m1 + m2));
    return make_float3(q[3], q[4], mc * (1.0f / 30.0f));
}

// (key,u,w) from a 15-float row in smem
__device__ __forceinline__ void feat_from_row(const float* q, int feat,
                                              float& key, float& u, float& w) {
    if (feat == 0)      { key = q[5]; u = key; w = 0.f; }
    else if (feat == 1) { key = q[7]; u = key; w = 0.f; }
    else if (feat == 2) { key = q[3]; u = key; w = 0.f; }
    else if (feat == 3) { key = q[4]; u = key; w = 0.f; }
    else if (feat == 4) {
        float msum = (q[0] + q[1]) * 95.0f + 10.0f;
        const float C = 3.1739290899557192f;          // 220*log2(e)/100
        float x = C * f_rcp(msum);
        key = x; u = f_ex2(x); w = f_ex2(-x);
    } else {
        float d = q[2] * 2950.0f + 50.0f;
        key = f_lg2(d); u = d; w = f_rcp(d);
    }
}

// exclusive prefix over 256 thread-values (tid order); all threads call.
__device__ __forceinline__ float excl_scan256(float val, float* warpTmp) {
    const int lane = threadIdx.x & 31, wid = threadIdx.x >> 5;
    float incl = val;
    #pragma unroll
    for (int off = 1; off < 32; off <<= 1) {
        float t = __shfl_up_sync(0xFFFFFFFFu, incl, off);
        if (lane >= off) incl += t;
    }
    __syncthreads();
    if (lane == 31) warpTmp[wid] = incl;
    __syncthreads();
    float base = 0.f;
    #pragma unroll
    for (int ww = 0; ww < 8; ++ww)
        base += (ww < wid) ? warpTmp[ww] : 0.f;
    return base + incl - val;
}

// in-place inclusive scan of arr[NB] with 256 threads (16 per thread)
__device__ __forceinline__ void incl_scan4096(float* arr, float* warpTmp) {
    const int base = threadIdx.x * 16;
    float seg = 0.f;
    #pragma unroll
    for (int q = 0; q < 16; ++q) seg += arr[base + q];
    float run = excl_scan256(seg, warpTmp);
    #pragma unroll
    for (int q = 0; q < 16; ++q) { run += arr[base + q]; arr[base + q] = run; }
}

// smem: 32KB buckets + 15KB staging + 64B scan tmp = 48.2KB (<= 48KB static? 49152)
#define OFF_STAGE (NB * 8)
#define OFF_WTMP  (NB * 8 + 15360)
#define SMEM_SZ   (NB * 8 + 15360 + 64)

// ---------------------------------------------------------------------------
// Fused kernel: 6 feature blocks + 128 pairwise blocks = 134 (one wave).
// ---------------------------------------------------------------------------
__global__ void __launch_bounds__(IB) fused_kernel(const float* __restrict__ p) {
    __shared__ __align__(16) unsigned char smraw[SMEM_SZ];
    const int tid = threadIdx.x;

    if (blockIdx.x < NFEAT) {
        // ============ FEATURE BLOCK: bucketed O(1) closed form ============
        const int feat = blockIdx.x;
        const bool isexp = (feat >= 4);
        float* sA      = (float*)(smraw);             // abs: incl count | exp: incl U
        float* sB      = (float*)(smraw + NB * 4);    // abs: incl U     | exp: incl W
        float* stage   = (float*)(smraw + OFF_STAGE); // 256 rows x 15 floats
        float* warpTmp = (float*)(smraw + OFF_WTMP);

        float lo, scale;
        if      (feat == 4) { lo = 0.01580f; scale = (float)NB / 0.30220f; }
        else if (feat == 5) { lo = 5.64350f; scale = (float)NB / 5.91200f; }
        else                { lo = 0.0f;     scale = (float)NB; }

        #pragma unroll
        for (int q = tid; q < NB; q += IB) { sA[q] = 0.f; sB[q] = 0.f; }

        // stage p coalesced, 256 rows at a time; cache (key,u,w) in registers
        float kk[16], uu[16], ww[16];
        #pragma unroll
        for (int c = 0; c < 16; ++c) {
            __syncthreads();
            #pragma unroll
            for (int t = tid; t < 256 * 15; t += IB)
                stage[t] = p[c * 256 * 15 + t];
            __syncthreads();
            feat_from_row(stage + tid * 15, feat, kk[c], uu[c], ww[c]);
        }
        __syncthreads();

        // pass 1: histogram + aggregates (register-cached values)
        #pragma unroll
        for (int c = 0; c < 16; ++c) {
            int b = min(NB - 1, max(0, (int)((kk[c] - lo) * scale)));
            if (isexp) { atomicAdd(&sA[b], uu[c]); atomicAdd(&sB[b], ww[c]); }
            else       { atomicAdd(&sA[b], 1.0f);  atomicAdd(&sB[b], uu[c]); }
        }
        __syncthreads();

        incl_scan4096(sA, warpTmp);
        __syncthreads();
        incl_scan4096(sB, warpTmp);
        __syncthreads();

        const float TotB = sB[NB - 1];

        // pass 2: O(1) closed form per element (self excluded exactly)
        #pragma unroll
        for (int c = 0; c < 16; ++c) {
            float u = uu[c], w = ww[c];
            int b = min(NB - 1, max(0, (int)((kk[c] - lo) * scale)));
            float res;
            if (isexp) {
                res = w * (sA[b] - u) + u * (TotB - sB[b]);
            } else {
                float cb = sA[b] - 1.0f;
                float ca = (float)N - sA[b];
                res = u * cb - (sB[b] - u) + (TotB - sB[b]) - u * ca;
            }
            g_closed[feat][c * 256 + tid] = res;
        }
        return;
    }

    // ============ PAIRWISE BLOCK: sky_sep + mass_sim ============
    float4* sj = (float4*)(smraw);      // [JC] {ra, dec, mc30, pad}
    const int pb = blockIdx.x - NFEAT;
    const int ib = pb & (NBI - 1);
    const int jb = pb >> 4;             // NBI = 16
    const int i  = ib * IB + tid;
    const int j0 = jb * JC;

    for (int k = tid; k < JC; k += IB) {
        float3 v = pair_inv(p, j0 + k);
        sj[k] = make_float4(v.x, v.y, v.z, 0.f);
    }
    float3 a = pair_inv(p, i);
    __syncthreads();

    float s_sky = 0.f, s_ms = 0.f;
    #pragma unroll 8
    for (int j = 0; j < JC; ++j) {
        const float4 b = sj[j];
        float dra = a.x - b.x;
        float dde = a.y - b.y;
        s_sky += f_sqrt(fmaf(dra, dra, dde * dde));
        s_ms  += f_rcp(1.0f + fabsf(a.z - b.z));
    }
    g_part2[jb][i] = make_float2(s_sky, s_ms);
}

// ---------------------------------------------------------------------------
// Finish: 8 lanes per row. 128 blocks x 256 threads.
// ---------------------------------------------------------------------------
#define FTB 256
__global__ void __launch_bounds__(FTB) finish_kernel(
    const float* __restrict__ W1, const float* __restrict__ b1,
    const float* __restrict__ ln_g, const float* __restrict__ ln_b,
    const float* __restrict__ W2, const float* __restrict__ b2,
    float* __restrict__ out)
{
    __shared__ float sW1[8 * 32];
    __shared__ float sW2[32 * 16];
    __shared__ float sb1[32], sg[32], sbeta[32], sb2[16];

    for (int k = threadIdx.x; k < 256; k += FTB) sW1[k] = W1[k];
    for (int k = threadIdx.x; k < 512; k += FTB) sW2[k] = W2[k];
    if (threadIdx.x < 32) {
        int k = threadIdx.x;
        sb1[k] = b1[k]; sg[k] = ln_g[k]; sbeta[k] = ln_b[k];
        if (k < 16) sb2[k] = b2[k];
    }
    __syncthreads();

    const int lane = threadIdx.x & 31;
    const int warp = threadIdx.x >> 5;
    const int sub  = lane & 7;
    const int rig  = lane >> 3;
    const int i    = blockIdx.x * 32 + warp * 4 + rig;

    // reduce pairwise partials: lane owns 1 of 8 chunks, butterfly over 8 lanes
    float2 pp = g_part2[sub][i];
    float t_sky = pp.x, t_ms = pp.y;
    #pragma unroll
    for (int m = 1; m < 8; m <<= 1) {
        t_sky += __shfl_xor_sync(0xFFFFFFFFu, t_sky, m);
        t_ms  += __shfl_xor_sync(0xFFFFFFFFu, t_ms,  m);
    }

    const float inv = 1.0f / (float)(N - 1);
    float x[8];
    x[0] = g_closed[0][i] * inv;
    x[1] = t_sky * inv;
    x[2] = (t_ms - 1.0f) * inv;
    x[3] = g_closed[4][i] * inv;
    x[4] = g_closed[5][i] * inv;
    x[5] = g_closed[1][i] * inv;
    x[6] = g_closed[2][i] * inv;
    x[7] = g_closed[3][i] * inv;

    const int k0 = sub * 4;
    float h[4];
    #pragma unroll
    for (int kk = 0; kk < 4; ++kk) {
        float acc = sb1[k0 + kk];
        #pragma unroll
        for (int f = 0; f < 8; ++f)
            acc = fmaf(x[f], sW1[f * 32 + k0 + kk], acc);
        h[kk] = acc;
    }

    float s1 = h[0] + h[1] + h[2] + h[3];
    #pragma unroll
    for (int m = 1; m < 8; m <<= 1) s1 += __shfl_xor_sync(0xFFFFFFFFu, s1, m);
    float mu = s1 * (1.0f / 32.0f);

    float s2 = 0.f;
    #pragma unroll
    for (int kk = 0; kk < 4; ++kk) {
        float d = h[kk] - mu;
        s2 = fmaf(d, d, s2);
    }
    #pragma unroll
    for (int m = 1; m < 8; m <<= 1) s2 += __shfl_xor_sync(0xFFFFFFFFu, s2, m);
    float rs = rsqrtf(s2 * (1.0f / 32.0f) + 1e-5f);

    #pragma unroll
    for (int kk = 0; kk < 4; ++kk) {
        float v = fmaf((h[kk] - mu) * rs, sg[k0 + kk], sbeta[k0 + kk]);
        h[kk] = 0.5f * v * (1.0f + erff(v * 0.7071067811865475f));
    }

    float o[16];
    #pragma unroll
    for (int oo = 0; oo < 16; ++oo) o[oo] = 0.f;
    #pragma unroll
    for (int kk = 0; kk < 4; ++kk) {
        #pragma unroll
        for (int oo = 0; oo < 16; ++oo)
            o[oo] = fmaf(h[kk], sW2[(k0 + kk) * 16 + oo], o[oo]);
    }
    #pragma unroll
    for (int m = 1; m < 8; m <<= 1) {
        #pragma unroll
        for (int oo = 0; oo < 16; ++oo)
            o[oo] += __shfl_xor_sync(0xFFFFFFFFu, o[oo], m);
    }

    if (sub == 0) {
        float4* op = reinterpret_cast<float4*>(out + i * 16);
        op[0] = make_float4(o[0]  + sb2[0],  o[1]  + sb2[1],
                            o[2]  + sb2[2],  o[3]  + sb2[3]);
        op[1] = make_float4(o[4]  + sb2[4],  o[5]  + sb2[5],
                            o[6]  + sb2[6],  o[7]  + sb2[7]);
        op[2] = make_float4(o[8]  + sb2[8],  o[9]  + sb2[9],
                            o[10] + sb2[10], o[11] + sb2[11]);
        op[3] = make_float4(o[12] + sb2[12], o[13] + sb2[13],
                            o[14] + sb2[14], o[15] + sb2[15]);
    }
}

extern "C" void kernel_launch(void* const* d_in, const int* in_sizes, int n_in,
                              void* d_out, int out_size) {
    const float* params = (const float*)d_in[0];
    const float* W1     = (const float*)d_in[1];
    const float* b1     = (const float*)d_in[2];
    const float* ln_g   = (const float*)d_in[3];
    const float* ln_b   = (const float*)d_in[4];
    const float* W2     = (const float*)d_in[5];
    const float* b2     = (const float*)d_in[6];
    float* out = (float*)d_out;

    fused_kernel<<<NFEAT + NBI * NJ, IB>>>(params);
    finish_kernel<<<N / 32, FTB>>>(W1, b1, ln_g, ln_b, W2, b2, out);
}